// round 6
// baseline (speedup 1.0000x reference)
#include <cuda_runtime.h>
#include <cuda_fp16.h>
#include <cstdint>
#include <math.h>

#define Bsz 8192
#define Hdim 1024
#define G4 4096
#define HG (1024 * 4096)

#define BM 128      // batch rows per CTA
#define BN 128      // permuted z-cols per CTA (= 32 units x 4 gates)
#define BK 64       // K per pipeline chunk
#define NCHUNK (Hdim / BK)   // 16
#define NSTAGE 3
#define NTH 256

#define STAGE_BYTES 32768    // A: 128x64 half = 16KB ; B: 64x128 half = 16KB
#define STB_OFF 16384
#define SMEM_TOTAL (NSTAGE * STAGE_BYTES + 1024)   // +1KB for 1024-alignment

// ---------------- device scratch (allocation-free) ----------------
__device__ __align__(256) __half g_W[4ull * HG];   // permuted fp16 weights
__device__ __align__(256) __half g_h0h[Bsz * Hdim];
__device__ __align__(256) __half g_hah[Bsz * Hdim];
__device__ __align__(256) __half g_hbh[Bsz * Hdim];
__device__ float  g_ca[Bsz * Hdim];
__device__ float  g_cb[Bsz * Hdim];
__device__ float  g_biasp[4 * G4];       // permuted biases per layer
__device__ float  g_wx0p[G4];            // permuted Wx0

// permuted column layout: n' = (u>>2)*16 + (gate>>1)*8 + (u&3)*2 + (gate&1)
__device__ __forceinline__ int np_to_col(int np) {
    int u = ((np >> 4) << 2) | ((np >> 1) & 3);
    int gate = (((np >> 3) & 1) << 1) | (np & 1);
    return gate * 1024 + u;
}

__device__ __forceinline__ uint32_t smem_u32(const void* p) {
    uint32_t a;
    asm("{ .reg .u64 t; cvta.to.shared.u64 t, %1; cvt.u32.u64 %0, t; }" : "=r"(a) : "l"(p));
    return a;
}
__device__ __forceinline__ float sigm(float z) { return 1.0f / (1.0f + __expf(-z)); }
__device__ __forceinline__ float tanha(float x) {
    float r; asm("tanh.approx.f32 %0, %1;" : "=f"(r) : "f"(x)); return r;
}

#define CP16(dst, src) \
    asm volatile("cp.async.cg.shared.global [%0], [%1], 16;" :: "r"(dst), "l"(src) : "memory")
#define CPCOMMIT() asm volatile("cp.async.commit_group;" ::: "memory")
#define CPWAIT(n)  asm volatile("cp.async.wait_group %0;" :: "n"(n) : "memory")

#define LDSM4(r0, r1, r2, r3, a)                                              \
    asm volatile("ldmatrix.sync.aligned.m8n8.x4.shared.b16 {%0,%1,%2,%3}, [%4];" \
                 : "=r"(r0), "=r"(r1), "=r"(r2), "=r"(r3) : "r"(a))
#define LDSM4T(r0, r1, r2, r3, a)                                             \
    asm volatile("ldmatrix.sync.aligned.m8n8.x4.trans.shared.b16 {%0,%1,%2,%3}, [%4];" \
                 : "=r"(r0), "=r"(r1), "=r"(r2), "=r"(r3) : "r"(a))

__device__ __forceinline__ void mma16816(float* d, const uint32_t* a,
                                         uint32_t b0, uint32_t b1) {
    asm volatile(
        "mma.sync.aligned.m16n8k16.row.col.f32.f16.f16.f32 "
        "{%0,%1,%2,%3}, {%4,%5,%6,%7}, {%8,%9}, {%0,%1,%2,%3};\n"
        : "+f"(d[0]), "+f"(d[1]), "+f"(d[2]), "+f"(d[3])
        : "r"(a[0]), "r"(a[1]), "r"(a[2]), "r"(a[3]), "r"(b0), "r"(b1));
}

// ---------------- prep kernels ----------------
__global__ void wprep_kernel(const float4* __restrict__ Wh0,
                             const float4* __restrict__ Wx,
                             const float4* __restrict__ Wh) {
    size_t idx = (size_t)blockIdx.x * blockDim.x + threadIdx.x;  // < 4*1024*256
    int u4 = (int)(idx & 255);
    size_t kl = idx >> 8;             // l*1024 + k
    int l = (int)(kl >> 10);
    size_t k = kl & 1023;
    __half out[16];
    #pragma unroll
    for (int gate = 0; gate < 4; gate++) {
        size_t col4 = (size_t)(gate * 1024 + u4 * 4) >> 2;
        float4 v;
        if (l == 0) {
            v = Wh0[k * 1024 + col4];
        } else {
            size_t o = (size_t)(l - 1) * (HG / 4) + k * 1024 + col4;
            float4 a = Wx[o], b = Wh[o];
            v.x = a.x + b.x; v.y = a.y + b.y; v.z = a.z + b.z; v.w = a.w + b.w;
        }
        int base = ((gate >> 1) << 3) | (gate & 1);
        out[base + 0] = __float2half_rn(v.x);
        out[base + 2] = __float2half_rn(v.y);
        out[base + 4] = __float2half_rn(v.z);
        out[base + 6] = __float2half_rn(v.w);
    }
    uint4* dst = (uint4*)(g_W + idx * 16);
    dst[0] = ((const uint4*)out)[0];
    dst[1] = ((const uint4*)out)[1];
}
__global__ void hprep_kernel(const float4* __restrict__ h0) {
    size_t i = (size_t)blockIdx.x * blockDim.x + threadIdx.x;  // < Bsz*Hdim/4
    float4 v = h0[i];
    __half2* d = (__half2*)(g_h0h + i * 4);
    d[0] = __floats2half2_rn(v.x, v.y);
    d[1] = __floats2half2_rn(v.z, v.w);
}
__global__ void bprep_kernel(const float* __restrict__ b0,
                             const float* __restrict__ bb,
                             const float* __restrict__ Wx0) {
    int idx = blockIdx.x * blockDim.x + threadIdx.x;   // < 5*4096
    int np = idx & 4095;
    int l = idx >> 12;
    int col = np_to_col(np);
    if (l < 4) {
        g_biasp[idx] = (l == 0) ? b0[col] : bb[(l - 1) * G4 + col];
    } else {
        g_wx0p[np] = Wx0[col];
    }
}

// ---------------- fused LSTM layer (fp16 mma.sync, XOR-addressed pipeline) --
__global__ void __launch_bounds__(NTH, 2)
lstm_layer_kernel(int layer,
                  const float* __restrict__ xvec,
                  const float* __restrict__ c0ext,
                  float* __restrict__ dout)
{
    const __half *A, *W;
    const float *c_in;
    float *c_out;
    __half *h_out_h;
    float *h_out_f;
    if (layer == 0) {
        A = g_h0h; c_in = c0ext; W = g_W;
        c_out = g_ca; h_out_h = g_hah; h_out_f = nullptr;
    } else if (layer == 1) {
        A = g_hah; c_in = g_ca; W = g_W + (size_t)HG;
        c_out = g_cb; h_out_h = g_hbh; h_out_f = nullptr;
    } else if (layer == 2) {
        A = g_hbh; c_in = g_cb; W = g_W + 2ull * HG;
        c_out = g_ca; h_out_h = g_hah; h_out_f = nullptr;
    } else {
        A = g_hah; c_in = g_ca; W = g_W + 3ull * HG;
        c_out = dout; h_out_h = nullptr; h_out_f = dout + (size_t)Bsz * Hdim;
    }
    const bool is_l0 = (layer == 0);
    const float* biasp = g_biasp + layer * G4;

    extern __shared__ char smem_raw[];
    const uint32_t sb = (smem_u32(smem_raw) + 1023u) & ~1023u;  // 1024-align for XOR addr
    const int tid  = threadIdx.x;
    const int lane = tid & 31;
    const int wid  = tid >> 5;
    const int wm   = wid >> 2;        // 0..1  (64 m rows each)
    const int wn   = wid & 3;         // 0..3  (32 n' cols each)
    const int rowBase = blockIdx.y * BM;
    const int nBase   = blockIdx.x * BN;

    const __half* Abase = A + (size_t)rowBase * Hdim;
    const __half* Wbase = W + nBase;

    // ---- cp.async chunk loader (all 256 threads) ----
    auto load_chunk = [&](int s, int c) {
        const uint32_t stA = sb + s * STAGE_BYTES;
        const uint32_t stB = stA + STB_OFF;
        #pragma unroll
        for (int q = 0; q < 8; q++) {
            int i = tid + q * 256;       // 0..2047
            uint32_t dst; const __half* src;
            if (i < 1024) {              // A: 128 rows x 8 units(16B)
                int r = i >> 3, k16 = i & 7;
                dst = stA + r * 128 + 16 * (k16 ^ (r & 7));
                src = Abase + (size_t)r * Hdim + c * BK + k16 * 8;
            } else {                     // B: 64 k-rows x 16 units
                int j = i - 1024;
                int k = j >> 4, n16 = j & 15;
                dst = stB + k * 256 + 16 * (n16 ^ (k & 7));
                src = Wbase + (size_t)(c * BK + k) * G4 + n16 * 8;
            }
            CP16(dst, src);
        }
        CPCOMMIT();
    };

    float acc[4][4][4];
    #pragma unroll
    for (int mt = 0; mt < 4; mt++)
        #pragma unroll
        for (int j = 0; j < 4; j++)
            #pragma unroll
            for (int r = 0; r < 4; r++) acc[mt][j][r] = 0.0f;

    // per-lane ldmatrix base-address components (ks=0)
    const int arow = wm * 64 + (lane & 15);              // per mt: +mt*16
    const int ahi  = lane >> 4;                          // 0/1 (k-half unit)
    const int bm   = lane >> 3;                          // matrix id 0..3
    const int br   = lane & 7;                           // row within 8
    const int bkoff = br + (bm & 1) * 8;                 // k row offset within 16
    const int bnunit = wn * 4 + (bm >> 1);               // n' 16B-unit

    // relative (stage-invariant) base offsets:
    //  A(ks) = stA + offA[mt] ^ (ks<<5)     (swizzle bits live in [4:6])
    //  B(ks) = stB + offB[jp] + ks*4096
    uint32_t offA[4], offB[2];
    #pragma unroll
    for (int mt = 0; mt < 4; mt++) {
        int rr = arow + mt * 16;
        offA[mt] = (uint32_t)(rr * 128 + 16 * (ahi ^ (rr & 7)));
    }
    #pragma unroll
    for (int jp = 0; jp < 2; jp++)
        offB[jp] = (uint32_t)(bkoff * 256 + 16 * ((bnunit + jp * 2) ^ (bkoff & 7)));

    uint32_t af[4][4];        // A frags, rolling per-mt reload
    uint32_t bf[2][4][2];     // B frags, double-buffered over ks

    // prologue: fill first two stages
    load_chunk(0, 0);
    load_chunk(1, 1);

    for (int c = 0; c < NCHUNK; c++) {
        const int s = c % NSTAGE;
        if (c + 1 < NCHUNK) { CPWAIT(1); } else { CPWAIT(0); }
        __syncthreads();

        const uint32_t stA = sb + s * STAGE_BYTES;
        const uint32_t stB = stA + STB_OFF;
        uint32_t aAddr[4];
        #pragma unroll
        for (int mt = 0; mt < 4; mt++) aAddr[mt] = stA + offA[mt];
        const uint32_t b0Addr = stB + offB[0];
        const uint32_t b1Addr = stB + offB[1];

        // ks=0 fragment loads (the only exposed burst per chunk)
        #pragma unroll
        for (int mt = 0; mt < 4; mt++)
            LDSM4(af[mt][0], af[mt][1], af[mt][2], af[mt][3], aAddr[mt]);
        {
            uint32_t r0, r1, r2, r3;
            LDSM4T(r0, r1, r2, r3, b0Addr);
            bf[0][0][0] = r0; bf[0][0][1] = r1; bf[0][1][0] = r2; bf[0][1][1] = r3;
            LDSM4T(r0, r1, r2, r3, b1Addr);
            bf[0][2][0] = r0; bf[0][2][1] = r1; bf[0][3][0] = r2; bf[0][3][1] = r3;
        }

        if (c + 2 < NCHUNK) load_chunk((c + 2) % NSTAGE, c + 2);

        #pragma unroll
        for (int ks = 0; ks < 4; ks++) {
            const int cur = ks & 1;
            const uint32_t axor = (uint32_t)((ks + 1) << 5);

            // mt0 mma group first, then prefetches ride in its tensor shadow
            #pragma unroll
            for (int j = 0; j < 4; j++)
                mma16816(acc[0][j], af[0], bf[cur][j][0], bf[cur][j][1]);
            if (ks < 3) {
                uint32_t r0, r1, r2, r3;
                LDSM4T(r0, r1, r2, r3, b0Addr + (ks + 1) * 4096);
                bf[cur ^ 1][0][0] = r0; bf[cur ^ 1][0][1] = r1;
                bf[cur ^ 1][1][0] = r2; bf[cur ^ 1][1][1] = r3;
                LDSM4T(r0, r1, r2, r3, b1Addr + (ks + 1) * 4096);
                bf[cur ^ 1][2][0] = r0; bf[cur ^ 1][2][1] = r1;
                bf[cur ^ 1][3][0] = r2; bf[cur ^ 1][3][1] = r3;
                LDSM4(af[0][0], af[0][1], af[0][2], af[0][3], aAddr[0] ^ axor);
            }
            #pragma unroll
            for (int mt = 1; mt < 4; mt++) {
                #pragma unroll
                for (int j = 0; j < 4; j++)
                    mma16816(acc[mt][j], af[mt], bf[cur][j][0], bf[cur][j][1]);
                if (ks < 3)
                    LDSM4(af[mt][0], af[mt][1], af[mt][2], af[mt][3],
                          aAddr[mt] ^ axor);
            }
        }
        // no trailing barrier: next iteration's CPWAIT+barrier provides ordering
    }

    // ---- epilogue: gates + cell update in-register ----
    const int a4 = lane & 3;
    #pragma unroll
    for (int mt = 0; mt < 4; mt++) {
        #pragma unroll
        for (int rh = 0; rh < 2; rh++) {
            const int row = rowBase + wm * 64 + mt * 16 + (lane >> 2) + rh * 8;
            const float xr = is_l0 ? xvec[row] : 0.0f;
            #pragma unroll
            for (int g16 = 0; g16 < 2; g16++) {
                const int nl = wn * 32 + g16 * 16 + a4 * 2;     // n' of gate0
                const int u  = blockIdx.x * 32 + wn * 8 + g16 * 4 + a4;
                float zi = acc[mt][g16 * 2 + 0][rh * 2 + 0] + biasp[nBase + nl];
                float zf = acc[mt][g16 * 2 + 0][rh * 2 + 1] + biasp[nBase + nl + 1];
                float zg = acc[mt][g16 * 2 + 1][rh * 2 + 0] + biasp[nBase + nl + 8];
                float zo = acc[mt][g16 * 2 + 1][rh * 2 + 1] + biasp[nBase + nl + 9];
                if (is_l0) {
                    zi += xr * g_wx0p[nBase + nl];
                    zf += xr * g_wx0p[nBase + nl + 1];
                    zg += xr * g_wx0p[nBase + nl + 8];
                    zo += xr * g_wx0p[nBase + nl + 9];
                }
                const float ig = sigm(zi);
                const float fg = sigm(zf);
                const float gg = tanha(zg);
                const float og = sigm(zo);
                const size_t off = (size_t)row * Hdim + u;
                const float cn = fg * c_in[off] + ig * gg;
                c_out[off] = cn;
                const float hv = og * tanha(cn);
                if (h_out_f) h_out_f[off] = hv;
                else         h_out_h[off] = __float2half_rn(hv);
            }
        }
    }
}

// ---------------- prediction head ----------------
__global__ void head_kernel(const float* __restrict__ h,
                            const float* __restrict__ Wd,
                            const float* __restrict__ bd,
                            float* __restrict__ out)
{
    int warpg = (blockIdx.x * blockDim.x + threadIdx.x) >> 5;
    int lane = threadIdx.x & 31;
    const float4* hp = (const float4*)(h + (size_t)warpg * Hdim);
    const float4* wp = (const float4*)Wd;
    float s = 0.0f;
    #pragma unroll
    for (int i = 0; i < 8; i++) {
        float4 a = hp[lane + i * 32];
        float4 w = wp[lane + i * 32];
        s += a.x * w.x + a.y * w.y + a.z * w.z + a.w * w.w;
    }
    #pragma unroll
    for (int o = 16; o; o >>= 1) s += __shfl_xor_sync(0xffffffffu, s, o);
    if (lane == 0) out[warpg] = s + bd[0];
}

extern "C" void kernel_launch(void* const* d_in, const int* in_sizes, int n_in,
                              void* d_out, int out_size)
{
    const float* x   = (const float*)d_in[0];
    const float* c0  = (const float*)d_in[1];
    const float* h0  = (const float*)d_in[2];
    const float* Wx0 = (const float*)d_in[3];
    const float* Wh0 = (const float*)d_in[4];
    const float* b0  = (const float*)d_in[5];
    const float* Wx  = (const float*)d_in[6];
    const float* Wh  = (const float*)d_in[7];
    const float* bb  = (const float*)d_in[8];
    const float* Wd  = (const float*)d_in[9];
    const float* bd  = (const float*)d_in[10];
    float* out = (float*)d_out;  // [c | h | x_pred]

    cudaFuncSetAttribute(lstm_layer_kernel,
                         cudaFuncAttributeMaxDynamicSharedMemorySize, SMEM_TOTAL);

    wprep_kernel<<<(4 * 1024 * 256) / 256, 256>>>((const float4*)Wh0,
                                                  (const float4*)Wx,
                                                  (const float4*)Wh);
    hprep_kernel<<<(Bsz * Hdim / 4) / 256, 256>>>((const float4*)h0);
    bprep_kernel<<<(5 * G4) / 256, 256>>>(b0, bb, Wx0);

    dim3 grid(G4 / BN, Bsz / BM);   // 32 x 64 = 2048 CTAs
    for (int l = 0; l < 4; l++)
        lstm_layer_kernel<<<grid, NTH, SMEM_TOTAL>>>(l, x, c0, out);

    head_kernel<<<Bsz / 8, 256>>>(out + (size_t)Bsz * Hdim, Wd, bd,
                                  out + 2ull * (size_t)Bsz * Hdim);
}

// round 7
// speedup vs baseline: 1.1378x; 1.1378x over previous
#include <cuda_runtime.h>
#include <cuda_fp16.h>
#include <cstdint>
#include <math.h>

#define Bsz 8192
#define Hdim 1024
#define G4 4096
#define HG (1024 * 4096)

#define BM 128      // batch rows per CTA
#define BN 128      // permuted z-cols per CTA (= 32 units x 4 gates)
#define BK 64       // K per pipeline chunk
#define NCHUNK (Hdim / BK)   // 16
#define NSTAGE 3
#define NTH 256

#define STAGE_BYTES 32768    // A: 128x64 half = 16KB ; B: 64x128 half = 16KB
#define STB_OFF 16384
#define SMEM_TOTAL (NSTAGE * STAGE_BYTES + 1024)   // +1KB for 1024-alignment

// ---------------- device scratch (allocation-free) ----------------
__device__ __align__(256) __half g_W[4ull * HG];   // permuted fp16 weights
__device__ __align__(256) __half g_h0h[Bsz * Hdim];
__device__ __align__(256) __half g_hah[Bsz * Hdim];
__device__ __align__(256) __half g_hbh[Bsz * Hdim];
__device__ float  g_ca[Bsz * Hdim];
__device__ float  g_cb[Bsz * Hdim];
__device__ float  g_biasp[4 * G4];       // permuted biases per layer
__device__ float  g_wx0p[G4];            // permuted Wx0

// permuted column layout: n' = (u>>2)*16 + (gate>>1)*8 + (u&3)*2 + (gate&1)
__device__ __forceinline__ int np_to_col(int np) {
    int u = ((np >> 4) << 2) | ((np >> 1) & 3);
    int gate = (((np >> 3) & 1) << 1) | (np & 1);
    return gate * 1024 + u;
}

__device__ __forceinline__ uint32_t smem_u32(const void* p) {
    uint32_t a;
    asm("{ .reg .u64 t; cvta.to.shared.u64 t, %1; cvt.u32.u64 %0, t; }" : "=r"(a) : "l"(p));
    return a;
}
__device__ __forceinline__ float sigm(float z) { return 1.0f / (1.0f + __expf(-z)); }
__device__ __forceinline__ float tanha(float x) {
    float r; asm("tanh.approx.f32 %0, %1;" : "=f"(r) : "f"(x)); return r;
}

#define CP16(dst, src) \
    asm volatile("cp.async.cg.shared.global [%0], [%1], 16;" :: "r"(dst), "l"(src) : "memory")
#define CPCOMMIT() asm volatile("cp.async.commit_group;" ::: "memory")
#define CPWAIT(n)  asm volatile("cp.async.wait_group %0;" :: "n"(n) : "memory")

#define LDSM4(r0, r1, r2, r3, a)                                              \
    asm volatile("ldmatrix.sync.aligned.m8n8.x4.shared.b16 {%0,%1,%2,%3}, [%4];" \
                 : "=r"(r0), "=r"(r1), "=r"(r2), "=r"(r3) : "r"(a))
#define LDSM4T(r0, r1, r2, r3, a)                                             \
    asm volatile("ldmatrix.sync.aligned.m8n8.x4.trans.shared.b16 {%0,%1,%2,%3}, [%4];" \
                 : "=r"(r0), "=r"(r1), "=r"(r2), "=r"(r3) : "r"(a))

__device__ __forceinline__ void mma16816(float* d, const uint32_t* a,
                                         uint32_t b0, uint32_t b1) {
    asm volatile(
        "mma.sync.aligned.m16n8k16.row.col.f32.f16.f16.f32 "
        "{%0,%1,%2,%3}, {%4,%5,%6,%7}, {%8,%9}, {%0,%1,%2,%3};\n"
        : "+f"(d[0]), "+f"(d[1]), "+f"(d[2]), "+f"(d[3])
        : "r"(a[0]), "r"(a[1]), "r"(a[2]), "r"(a[3]), "r"(b0), "r"(b1));
}

// ---------------- prep kernels ----------------
__global__ void wprep_kernel(const float4* __restrict__ Wh0,
                             const float4* __restrict__ Wx,
                             const float4* __restrict__ Wh) {
    size_t idx = (size_t)blockIdx.x * blockDim.x + threadIdx.x;  // < 4*1024*256
    int u4 = (int)(idx & 255);
    size_t kl = idx >> 8;             // l*1024 + k
    int l = (int)(kl >> 10);
    size_t k = kl & 1023;
    __half out[16];
    #pragma unroll
    for (int gate = 0; gate < 4; gate++) {
        size_t col4 = (size_t)(gate * 1024 + u4 * 4) >> 2;
        float4 v;
        if (l == 0) {
            v = Wh0[k * 1024 + col4];
        } else {
            size_t o = (size_t)(l - 1) * (HG / 4) + k * 1024 + col4;
            float4 a = Wx[o], b = Wh[o];
            v.x = a.x + b.x; v.y = a.y + b.y; v.z = a.z + b.z; v.w = a.w + b.w;
        }
        int base = ((gate >> 1) << 3) | (gate & 1);
        out[base + 0] = __float2half_rn(v.x);
        out[base + 2] = __float2half_rn(v.y);
        out[base + 4] = __float2half_rn(v.z);
        out[base + 6] = __float2half_rn(v.w);
    }
    uint4* dst = (uint4*)(g_W + idx * 16);
    dst[0] = ((const uint4*)out)[0];
    dst[1] = ((const uint4*)out)[1];
}
__global__ void hprep_kernel(const float4* __restrict__ h0) {
    size_t i = (size_t)blockIdx.x * blockDim.x + threadIdx.x;  // < Bsz*Hdim/4
    float4 v = h0[i];
    __half2* d = (__half2*)(g_h0h + i * 4);
    d[0] = __floats2half2_rn(v.x, v.y);
    d[1] = __floats2half2_rn(v.z, v.w);
}
__global__ void bprep_kernel(const float* __restrict__ b0,
                             const float* __restrict__ bb,
                             const float* __restrict__ Wx0) {
    int idx = blockIdx.x * blockDim.x + threadIdx.x;   // < 5*4096
    int np = idx & 4095;
    int l = idx >> 12;
    int col = np_to_col(np);
    if (l < 4) {
        g_biasp[idx] = (l == 0) ? b0[col] : bb[(l - 1) * G4 + col];
    } else {
        g_wx0p[np] = Wx0[col];
    }
}

// ------- fused LSTM layer (fp16 mma.sync, cross-chunk fragment pipeline) ----
__global__ void __launch_bounds__(NTH, 2)
lstm_layer_kernel(int layer,
                  const float* __restrict__ xvec,
                  const float* __restrict__ c0ext,
                  float* __restrict__ dout)
{
    const __half *A, *W;
    const float *c_in;
    float *c_out;
    __half *h_out_h;
    float *h_out_f;
    if (layer == 0) {
        A = g_h0h; c_in = c0ext; W = g_W;
        c_out = g_ca; h_out_h = g_hah; h_out_f = nullptr;
    } else if (layer == 1) {
        A = g_hah; c_in = g_ca; W = g_W + (size_t)HG;
        c_out = g_cb; h_out_h = g_hbh; h_out_f = nullptr;
    } else if (layer == 2) {
        A = g_hbh; c_in = g_cb; W = g_W + 2ull * HG;
        c_out = g_ca; h_out_h = g_hah; h_out_f = nullptr;
    } else {
        A = g_hah; c_in = g_ca; W = g_W + 3ull * HG;
        c_out = dout; h_out_h = nullptr; h_out_f = dout + (size_t)Bsz * Hdim;
    }
    const bool is_l0 = (layer == 0);
    const float* biasp = g_biasp + layer * G4;

    extern __shared__ char smem_raw[];
    const uint32_t sb = (smem_u32(smem_raw) + 1023u) & ~1023u;  // 1024-align
    const int tid  = threadIdx.x;
    const int lane = tid & 31;
    const int wid  = tid >> 5;
    const int wm   = wid >> 2;        // 0..1  (64 m rows each)
    const int wn   = wid & 3;         // 0..3  (32 n' cols each)
    const int rowBase = blockIdx.y * BM;
    const int nBase   = blockIdx.x * BN;

    const __half* Abase = A + (size_t)rowBase * Hdim;
    const __half* Wbase = W + nBase;

    // ---- cp.async chunk loader (all 256 threads) ----
    auto load_chunk = [&](int s, int c) {
        const uint32_t stA = sb + s * STAGE_BYTES;
        const uint32_t stB = stA + STB_OFF;
        #pragma unroll
        for (int q = 0; q < 8; q++) {
            int i = tid + q * 256;       // 0..2047
            uint32_t dst; const __half* src;
            if (i < 1024) {              // A: 128 rows x 8 units(16B)
                int r = i >> 3, k16 = i & 7;
                dst = stA + r * 128 + 16 * (k16 ^ (r & 7));
                src = Abase + (size_t)r * Hdim + c * BK + k16 * 8;
            } else {                     // B: 64 k-rows x 16 units
                int j = i - 1024;
                int k = j >> 4, n16 = j & 15;
                dst = stB + k * 256 + 16 * (n16 ^ (k & 7));
                src = Wbase + (size_t)(c * BK + k) * G4 + n16 * 8;
            }
            CP16(dst, src);
        }
        CPCOMMIT();
    };

    float acc[4][4][4];
    #pragma unroll
    for (int mt = 0; mt < 4; mt++)
        #pragma unroll
        for (int j = 0; j < 4; j++)
            #pragma unroll
            for (int r = 0; r < 4; r++) acc[mt][j][r] = 0.0f;

    // per-lane ldmatrix base-address components (ks=0)
    const int arow = wm * 64 + (lane & 15);              // per mt: +mt*16
    const int ahi  = lane >> 4;                          // 0/1 (k-half unit)
    const int bm   = lane >> 3;                          // matrix id 0..3
    const int br   = lane & 7;                           // row within 8
    const int bkoff = br + (bm & 1) * 8;                 // k row offset within 16
    const int bnunit = wn * 4 + (bm >> 1);               // n' 16B-unit

    // stage-invariant offsets:  A(ks) = stA + offA[mt] ^ (ks<<5)
    //                           B(ks) = stB + offB[jp] + ks*4096
    uint32_t offA[4], offB[2];
    #pragma unroll
    for (int mt = 0; mt < 4; mt++) {
        int rr = arow + mt * 16;
        offA[mt] = (uint32_t)(rr * 128 + 16 * (ahi ^ (rr & 7)));
    }
    #pragma unroll
    for (int jp = 0; jp < 2; jp++)
        offB[jp] = (uint32_t)(bkoff * 256 + 16 * ((bnunit + jp * 2) ^ (bkoff & 7)));

    uint32_t af[4][4];        // A frags, rolling per-mt reload
    uint32_t bf[2][4][2];     // B frags, double-buffered over ks

    // one ks-step: mma for all mt with bf[cur]; optional prefetch of the
    // NEXT ks-step's fragments (addresses given), placed in the tensor shadow.
    auto ksstep = [&](int cur, bool pf,
                      uint32_t pa0, uint32_t pa1, uint32_t pa2, uint32_t pa3,
                      uint32_t pb0, uint32_t pb1) {
        #pragma unroll
        for (int j = 0; j < 4; j++)
            mma16816(acc[0][j], af[0], bf[cur][j][0], bf[cur][j][1]);
        if (pf) {
            uint32_t r0, r1, r2, r3;
            LDSM4T(r0, r1, r2, r3, pb0);
            bf[cur ^ 1][0][0] = r0; bf[cur ^ 1][0][1] = r1;
            bf[cur ^ 1][1][0] = r2; bf[cur ^ 1][1][1] = r3;
            LDSM4T(r0, r1, r2, r3, pb1);
            bf[cur ^ 1][2][0] = r0; bf[cur ^ 1][2][1] = r1;
            bf[cur ^ 1][3][0] = r2; bf[cur ^ 1][3][1] = r3;
            LDSM4(af[0][0], af[0][1], af[0][2], af[0][3], pa0);
        }
        #pragma unroll
        for (int j = 0; j < 4; j++)
            mma16816(acc[1][j], af[1], bf[cur][j][0], bf[cur][j][1]);
        if (pf) LDSM4(af[1][0], af[1][1], af[1][2], af[1][3], pa1);
        #pragma unroll
        for (int j = 0; j < 4; j++)
            mma16816(acc[2][j], af[2], bf[cur][j][0], bf[cur][j][1]);
        if (pf) LDSM4(af[2][0], af[2][1], af[2][2], af[2][3], pa2);
        #pragma unroll
        for (int j = 0; j < 4; j++)
            mma16816(acc[3][j], af[3], bf[cur][j][0], bf[cur][j][1]);
        if (pf) LDSM4(af[3][0], af[3][1], af[3][2], af[3][3], pa3);
    };

    // prologue: fill first two stages, then the ONE exposed fragment load
    load_chunk(0, 0);
    load_chunk(1, 1);
    CPWAIT(1);
    __syncthreads();
    {
        const uint32_t stA = sb;
        const uint32_t stB = stA + STB_OFF;
        #pragma unroll
        for (int mt = 0; mt < 4; mt++)
            LDSM4(af[mt][0], af[mt][1], af[mt][2], af[mt][3], stA + offA[mt]);
        uint32_t r0, r1, r2, r3;
        LDSM4T(r0, r1, r2, r3, stB + offB[0]);
        bf[0][0][0] = r0; bf[0][0][1] = r1; bf[0][1][0] = r2; bf[0][1][1] = r3;
        LDSM4T(r0, r1, r2, r3, stB + offB[1]);
        bf[0][2][0] = r0; bf[0][2][1] = r1; bf[0][3][0] = r2; bf[0][3][1] = r3;
    }

    for (int c = 0; c < NCHUNK; c++) {
        const int s = c % NSTAGE;
        const uint32_t stA = sb + s * STAGE_BYTES;
        const uint32_t stB = stA + STB_OFF;
        uint32_t aA[4];
        #pragma unroll
        for (int mt = 0; mt < 4; mt++) aA[mt] = stA + offA[mt];
        const uint32_t b0A = stB + offB[0];
        const uint32_t b1A = stB + offB[1];
        const int sn = (c + 1) % NSTAGE;
        const uint32_t nA = sb + sn * STAGE_BYTES;
        const uint32_t nB = nA + STB_OFF;

        // ks=0, ks=1 (prefetch next ks within this stage)
        ksstep(0, true, aA[0] ^ 32u, aA[1] ^ 32u, aA[2] ^ 32u, aA[3] ^ 32u,
               b0A + 4096, b1A + 4096);
        ksstep(1, true, aA[0] ^ 64u, aA[1] ^ 64u, aA[2] ^ 64u, aA[3] ^ 64u,
               b0A + 8192, b1A + 8192);

        // mid-chunk sync: g(c+1) complete for everyone; stage (c+2)%3 free
        CPWAIT(0);
        __syncthreads();
        if (c + 2 < NCHUNK) load_chunk((c + 2) % NSTAGE, c + 2);

        // ks=2 (prefetch ks=3), ks=3 (prefetch NEXT CHUNK's ks=0)
        ksstep(0, true, aA[0] ^ 96u, aA[1] ^ 96u, aA[2] ^ 96u, aA[3] ^ 96u,
               b0A + 12288, b1A + 12288);
        const bool pf = (c + 1 < NCHUNK);
        ksstep(1, pf, nA + offA[0], nA + offA[1], nA + offA[2], nA + offA[3],
               nB + offB[0], nB + offB[1]);
    }

    // ---- epilogue: gates + cell update in-register ----
    const int a4 = lane & 3;
    #pragma unroll
    for (int mt = 0; mt < 4; mt++) {
        #pragma unroll
        for (int rh = 0; rh < 2; rh++) {
            const int row = rowBase + wm * 64 + mt * 16 + (lane >> 2) + rh * 8;
            const float xr = is_l0 ? xvec[row] : 0.0f;
            #pragma unroll
            for (int g16 = 0; g16 < 2; g16++) {
                const int nl = wn * 32 + g16 * 16 + a4 * 2;     // n' of gate0
                const int u  = blockIdx.x * 32 + wn * 8 + g16 * 4 + a4;
                float zi = acc[mt][g16 * 2 + 0][rh * 2 + 0] + biasp[nBase + nl];
                float zf = acc[mt][g16 * 2 + 0][rh * 2 + 1] + biasp[nBase + nl + 1];
                float zg = acc[mt][g16 * 2 + 1][rh * 2 + 0] + biasp[nBase + nl + 8];
                float zo = acc[mt][g16 * 2 + 1][rh * 2 + 1] + biasp[nBase + nl + 9];
                if (is_l0) {
                    zi += xr * g_wx0p[nBase + nl];
                    zf += xr * g_wx0p[nBase + nl + 1];
                    zg += xr * g_wx0p[nBase + nl + 8];
                    zo += xr * g_wx0p[nBase + nl + 9];
                }
                const float ig = sigm(zi);
                const float fg = sigm(zf);
                const float gg = tanha(zg);
                const float og = sigm(zo);
                const size_t off = (size_t)row * Hdim + u;
                const float cn = fg * c_in[off] + ig * gg;
                c_out[off] = cn;
                const float hv = og * tanha(cn);
                if (h_out_f) h_out_f[off] = hv;
                else         h_out_h[off] = __float2half_rn(hv);
            }
        }
    }
}

// ---------------- prediction head ----------------
__global__ void head_kernel(const float* __restrict__ h,
                            const float* __restrict__ Wd,
                            const float* __restrict__ bd,
                            float* __restrict__ out)
{
    int warpg = (blockIdx.x * blockDim.x + threadIdx.x) >> 5;
    int lane = threadIdx.x & 31;
    const float4* hp = (const float4*)(h + (size_t)warpg * Hdim);
    const float4* wp = (const float4*)Wd;
    float s = 0.0f;
    #pragma unroll
    for (int i = 0; i < 8; i++) {
        float4 a = hp[lane + i * 32];
        float4 w = wp[lane + i * 32];
        s += a.x * w.x + a.y * w.y + a.z * w.z + a.w * w.w;
    }
    #pragma unroll
    for (int o = 16; o; o >>= 1) s += __shfl_xor_sync(0xffffffffu, s, o);
    if (lane == 0) out[warpg] = s + bd[0];
}

extern "C" void kernel_launch(void* const* d_in, const int* in_sizes, int n_in,
                              void* d_out, int out_size)
{
    const float* x   = (const float*)d_in[0];
    const float* c0  = (const float*)d_in[1];
    const float* h0  = (const float*)d_in[2];
    const float* Wx0 = (const float*)d_in[3];
    const float* Wh0 = (const float*)d_in[4];
    const float* b0  = (const float*)d_in[5];
    const float* Wx  = (const float*)d_in[6];
    const float* Wh  = (const float*)d_in[7];
    const float* bb  = (const float*)d_in[8];
    const float* Wd  = (const float*)d_in[9];
    const float* bd  = (const float*)d_in[10];
    float* out = (float*)d_out;  // [c | h | x_pred]

    cudaFuncSetAttribute(lstm_layer_kernel,
                         cudaFuncAttributeMaxDynamicSharedMemorySize, SMEM_TOTAL);

    wprep_kernel<<<(4 * 1024 * 256) / 256, 256>>>((const float4*)Wh0,
                                                  (const float4*)Wx,
                                                  (const float4*)Wh);
    hprep_kernel<<<(Bsz * Hdim / 4) / 256, 256>>>((const float4*)h0);
    bprep_kernel<<<(5 * G4) / 256, 256>>>(b0, bb, Wx0);

    dim3 grid(G4 / BN, Bsz / BM);   // 32 x 64 = 2048 CTAs
    for (int l = 0; l < 4; l++)
        lstm_layer_kernel<<<grid, NTH, SMEM_TOTAL>>>(l, x, c0, out);

    head_kernel<<<Bsz / 8, 256>>>(out + (size_t)Bsz * Hdim, Wd, bd,
                                  out + 2ull * (size_t)Bsz * Hdim);
}